// round 12
// baseline (speedup 1.0000x reference)
#include <cuda_runtime.h>
#include <cuda_bf16.h>
#include <math.h>
#include <stdint.h>

#define N_MLP  16
#define LATENT 1024
#define S0     512
#define S1     256
#define S2     128
#define OUTD   3
#define TG     128
#define NTHR   256

// ---------------- SMEM layout (bytes) --------------------------------
// H1 tiles q=0..3: q*32768 (hi 16K | lo 16K)             0      .. 131072
// EVW / B2 double buffers (aliased, phase-disjoint)      131072 .. 196608
// b1f 256f @196608 | b2f 128f @197632 | w3f 384f @198144
// evk u16[1024] @199680 | evab float2[1024] @201728 | emc u8[1024] @209920
#define H1HI_OFF(q) ((q)*32768u)
#define H1LO_OFF(q) ((q)*32768u + 16384u)
#define EVW_OFF(b)  (131072u + (b)*32768u)
#define B2HI_OFF(b) (131072u + (b)*32768u)
#define B2LO_OFF(b) (131072u + (b)*32768u + 16384u)
#define EVK_OFF   199680u
#define EVAB_OFF  201728u
#define EMC_OFF   209920u
#define SMEM_TOTAL 210944u

#define SWZ(x) ((x) ^ (((x) >> 3) & 0x70u))

// ---------------- device scratch --------------------------------------
__device__ __align__(16) float         g_W1t [N_MLP * S0 * S1];   // [m][k][o]
__device__ __align__(16) __nv_bfloat16 g_W2hi[N_MLP * S2 * S1];
__device__ __align__(16) __nv_bfloat16 g_W2lo[N_MLP * S2 * S1];
__device__ float g_c0[N_MLP * S0];
__device__ __align__(16) uint16_t g_evk [N_MLP * 128 * 1024];
__device__ __align__(16) float2   g_evab[N_MLP * 128 * 1024];
__device__ __align__(16) uint8_t  g_emc [N_MLP * 128 * 1024];
__device__ uint2 g_meta[N_MLP * 128];   // {nep, pel}

// ---------------- helpers ---------------------------------------------
__device__ __forceinline__ uint32_t smem_u32(const void* p) {
    uint32_t a;
    asm("{ .reg .u64 t; cvta.to.shared.u64 t, %1; cvt.u32.u64 %0, t; }"
        : "=r"(a) : "l"(p));
    return a;
}
__device__ __forceinline__ void ldsm4(uint32_t* r, uint32_t addr) {
    asm volatile("ldmatrix.sync.aligned.m8n8.x4.shared.b16 {%0,%1,%2,%3}, [%4];"
                 : "=r"(r[0]), "=r"(r[1]), "=r"(r[2]), "=r"(r[3]) : "r"(addr));
}
__device__ __forceinline__ void mma_bf16(float* d, const uint32_t* a, const uint32_t* b) {
    asm volatile(
        "mma.sync.aligned.m16n8k16.row.col.f32.bf16.bf16.f32 "
        "{%0,%1,%2,%3}, {%4,%5,%6,%7}, {%8,%9}, {%0,%1,%2,%3};"
        : "+f"(d[0]), "+f"(d[1]), "+f"(d[2]), "+f"(d[3])
        : "r"(a[0]), "r"(a[1]), "r"(a[2]), "r"(a[3]), "r"(b[0]), "r"(b[1]));
}
__device__ __forceinline__ void cpa16(uint32_t dst, const void* src) {
    asm volatile("cp.async.cg.shared.global [%0], [%1], 16;"
                 :: "r"(dst), "l"(src) : "memory");
}
#define CP_COMMIT() asm volatile("cp.async.commit_group;" ::: "memory")
#define CP_WAIT1()  asm volatile("cp.async.wait_group 1;" ::: "memory")
#define CP_WAIT0()  asm volatile("cp.async.wait_group 0;" ::: "memory")

// ---------------- prep: c0 --------------------------------------------
__global__ void prep_c0(const float* __restrict__ x0,
                        const float* __restrict__ W0a,
                        const float* __restrict__ b0a,
                        const float* __restrict__ b0b) {
    int w    = (blockIdx.x * blockDim.x + threadIdx.x) >> 5;
    int lane = threadIdx.x & 31;
    if (w >= N_MLP * S0) return;
    const float* row = W0a + (size_t)w * LATENT;
    float s = 0.f;
    #pragma unroll 4
    for (int i = lane; i < LATENT; i += 32) s += row[i] * x0[i];
    #pragma unroll
    for (int off = 16; off; off >>= 1) s += __shfl_xor_sync(0xffffffffu, s, off);
    if (lane == 0) g_c0[w] = s + b0a[w] + b0b[w];
}

// ---------------- prep: W1 transpose via 32x33 tiles --------------------
__global__ void prep_w1t(const float* __restrict__ W1) {
    __shared__ float tl[32][33];
    int b = blockIdx.x;                 // m*128 + kt*8 + ot
    int m = b >> 7, rem = b & 127, kt = rem >> 3, ot = rem & 7;
    int tx = threadIdx.x & 31, ty = threadIdx.x >> 5;   // 256 thr
    const float* src = W1 + ((size_t)m * 256 + ot * 32) * 512 + kt * 32;
    #pragma unroll
    for (int j = 0; j < 4; ++j)
        tl[ty + j * 8][tx] = src[(size_t)(ty + j * 8) * 512 + tx];
    __syncthreads();
    float* dst = g_W1t + ((size_t)m * 512 + kt * 32) * 256 + ot * 32;
    #pragma unroll
    for (int j = 0; j < 4; ++j)
        dst[(size_t)(ty + j * 8) * 256 + tx] = tl[tx][ty + j * 8];
}

// ---------------- prep: W2 split ----------------------------------------
__global__ void prep_w2(const float* __restrict__ W2) {
    const int t2 = N_MLP * S2 * S1;
    for (int i = blockIdx.x * blockDim.x + threadIdx.x; i < t2;
         i += gridDim.x * blockDim.x) {
        float v = W2[i];
        __nv_bfloat16 h = __float2bfloat16(v);
        g_W2hi[i] = h;
        g_W2lo[i] = __float2bfloat16(v - __bfloat162float(h));
    }
}

// ---------------- prep: ReLU crossing events (parallel scatter) ---------
__device__ __forceinline__ bool actv(float wx, float al, float step, int rr) {
    return fmaf(wx, fmaf(step, (float)rr, -1.0f), al) > 0.0f;
}

__global__ void prep_events(const float* __restrict__ W0b,
                            const int*   __restrict__ n_ptr) {
    __shared__ float    salf[512], sbet[512];
    __shared__ int      slohi[512];
    __shared__ int      scnt[129];
    __shared__ int      cA[128][4], cR[128][4];
    __shared__ __align__(16) uint16_t sevk[1024];
    __shared__ __align__(16) float2   sevab[1024];
    __shared__ __align__(16) uint8_t  serow[1028];
    __shared__ __align__(16) uint8_t  semc[1024];

    const int tile = blockIdx.x, m = blockIdx.y, t = threadIdx.x;  // 512 thr
    const int n = *n_ptr;
    const float step = 2.0f / (float)(n - 1);
    const float gy = __fmaf_rn(step, (float)tile, -1.0f);

    if (t < 129) scnt[t] = 0;

    // phase 1: per-neuron boundary (1 k per thread, analytic + exact fixup)
    {
        const int k = t;
        float c0 = g_c0[m * 512 + k];
        float wx = W0b[(size_t)(m * 512 + k) * 2];
        float wy = W0b[(size_t)(m * 512 + k) * 2 + 1];
        float al = __fmaf_rn(wy, gy, c0);
        int lo, hi;
        if (wx > 0.0f) {
            float rf = (1.0f - al / wx) / step;
            int c = (int)floorf(rf) - 2;
            c = c < 0 ? 0 : (c > 128 ? 128 : c);
            while (c < 128 && !actv(wx, al, step, c)) ++c;
            while (c > 0 && actv(wx, al, step, c - 1)) --c;
            lo = c; hi = 128;
        } else if (wx < 0.0f) {
            if (!actv(wx, al, step, 0)) { lo = 128; hi = 128; }
            else {
                float rf = (1.0f - al / wx) / step;
                int c = (int)floorf(rf) - 2;
                c = c < 1 ? 1 : (c > 128 ? 128 : c);
                while (c < 128 && actv(wx, al, step, c)) ++c;
                while (c > 1 && !actv(wx, al, step, c - 1)) --c;
                lo = 0; hi = c;
            }
        } else {
            if (al > 0.0f) { lo = 0; hi = 128; } else { lo = 128; hi = 128; }
        }
        salf[k] = al; sbet[k] = wx; slohi[k] = (lo << 8) | hi;
    }
    __syncthreads();

    // phase 2: bucket counts
    {
        int v = slohi[t], lo = v >> 8, hi = v & 255;
        if (lo < hi) {
            atomicAdd(&scnt[lo + 1], 1);
            if (hi < 128) atomicAdd(&scnt[hi + 1], 1);
        }
    }
    __syncthreads();

    // phase 3: inclusive scan over scnt[1..128] (Hillis-Steele, 7 steps)
    #pragma unroll
    for (int d = 1; d < 128; d <<= 1) {
        int v = 0;
        if (t < 128) { int i = t + 1; if (i - d >= 1) v = scnt[i - d]; }
        __syncthreads();
        if (t < 128) scnt[t + 1] += v;
        __syncthreads();
    }

    // phase 4: per-(bucket,part) ADD/REMOVE counts; thread = b*?? -> b=t>>2, p=t&3
    const int b = t >> 2, p = t & 3;
    {
        int nA = 0, nR = 0;
        const int k0 = p * 128;
        for (int k = k0; k < k0 + 128; ++k) {
            int v = slohi[k], lo = v >> 8, hi = v & 255;
            if (lo < hi) {
                if (lo == b) ++nA;
                if (hi == b) ++nR;     // b <= 127 implies hi < 128
            }
        }
        cA[b][p] = nA; cR[b][p] = nR;
    }
    __syncthreads();

    // phase 5+6: exact offsets + deterministic scatter (ADDs k-asc, then REMOVEs k-asc)
    {
        int baseb = scnt[b];
        int totA = cA[b][0] + cA[b][1] + cA[b][2] + cA[b][3];
        int offA = baseb, offR = baseb + totA;
        #pragma unroll
        for (int pp = 0; pp < 4; ++pp)
            if (pp < p) { offA += cA[b][pp]; offR += cR[b][pp]; }
        const int k0 = p * 128;
        for (int k = k0; k < k0 + 128; ++k) {
            int v = slohi[k], lo = v >> 8, hi = v & 255;
            if (lo < hi) {
                if (lo == b) {
                    sevk[offA] = (uint16_t)k;
                    sevab[offA] = make_float2(salf[k], sbet[k]); ++offA;
                }
                if (hi == b) {
                    sevk[offR] = (uint16_t)k;
                    sevab[offR] = make_float2(-salf[k], -sbet[k]); ++offR;
                }
            }
        }
    }
    __syncthreads();

    const int ne = scnt[128];
    const int nep = (ne + 31) & ~31;
    for (int i = ne + t; i < 1024; i += 512) {
        sevk[i] = 0; sevab[i] = make_float2(0.f, 0.f);
    }
    for (int i = ne + t; i <= 1024; i += 512) serow[i] = 128;
    if (p == 0) for (int e = scnt[b]; e < scnt[b + 1]; ++e) serow[e] = (uint8_t)b;
    __syncthreads();
    for (int e = t; e < 1024; e += 512) semc[e] = serow[e + 1] - serow[e];
    __syncthreads();

    const size_t base = (size_t)m * gridDim.x + tile;
    if (t == 0) g_meta[base] = make_uint2((uint32_t)nep, (uint32_t)serow[0]);
    if (t < 128) ((uint4*)(g_evk + base * 1024))[t] = ((uint4*)sevk)[t];
    ((uint4*)(g_evab + base * 1024))[t] = ((uint4*)sevab)[t];
    if (t < 64) ((uint4*)(g_emc + base * 1024))[t] = ((uint4*)semc)[t];
}

// ---------------- main kernel (R11-verbatim) -----------------------------
__global__ __launch_bounds__(NTHR, 1)
void mlp_sweep(const float* __restrict__ b1,
               const float* __restrict__ b2,
               const float* __restrict__ W3,
               const float* __restrict__ b3,
               const int*   __restrict__ n_ptr,
               float*       __restrict__ out,
               int G) {
    extern __shared__ char smch[];
    const uint32_t smb = smem_u32(smch);
    float*    b1f  = (float*)(smch + 196608);
    float*    b2f  = (float*)(smch + 197632);
    float*    w3f  = (float*)(smch + 198144);
    uint16_t* evk  = (uint16_t*)(smch + EVK_OFF);
    float2*   evab = (float2*)(smch + EVAB_OFF);
    uint8_t*  emc  = (uint8_t*)(smch + EMC_OFF);

    const int m = blockIdx.y, tile = blockIdx.x;
    const int tid = threadIdx.x, w = tid >> 5, lane = tid & 31;
    const int n = *n_ptr;
    const float step = 2.0f / (float)(n - 1);

    // ---- stage consts + events ----
    b1f[tid] = b1[m * 256 + tid];
    if (tid < 128) b2f[tid] = b2[m * 128 + tid];
    for (int i = tid; i < 384; i += NTHR) w3f[i] = W3[(size_t)m * 384 + i];
    const size_t evbase = (size_t)m * gridDim.x + tile;
    if (tid < 128) ((uint4*)evk)[tid] = ((const uint4*)(g_evk + evbase * 1024))[tid];
    #pragma unroll
    for (int j = 0; j < 2; ++j)
        ((uint4*)evab)[tid + j * NTHR] =
            ((const uint4*)(g_evab + evbase * 1024))[tid + j * NTHR];
    if (tid < 64) ((uint4*)emc)[tid] = ((const uint4*)(g_emc + evbase * 1024))[tid];
    const uint2 meta = g_meta[evbase];
    const int nep = (int)meta.x;
    int pel = (int)meta.y;
    __syncthreads();

    const int nchunks = nep >> 5;

    #define STAGE_EVW(c) do {                                                  \
        int bb = (c) & 1;                                                      \
        _Pragma("unroll")                                                      \
        for (int jj = 0; jj < 8; ++jj) {                                       \
            int idx = tid + jj * NTHR;                                         \
            int row = idx >> 6, c16 = idx & 63;                                \
            int k = (int)evk[(c) * 32 + row];                                  \
            cpa16(smb + EVW_OFF(bb) + (uint32_t)(row * 1024 + c16 * 16),       \
                  g_W1t + ((size_t)m * 512 + k) * 256 + c16 * 4);              \
        }                                                                      \
        CP_COMMIT();                                                           \
    } while (0)

    if (nchunks > 0) { STAGE_EVW(0); if (nchunks > 1) STAGE_EVW(1); }

    // ---- layer1 flat event sweep: thread t owns column o = t ----
    {
        const float b1o = b1f[tid];
        const uint32_t qd = (uint32_t)tid >> 6;
        const uint32_t cbyte = (uint32_t)((tid & 63) * 2);
        float P = 0.f, Q = 0.f;
        int r = 0, e = 0;

        #define EMIT_ROW() do {                                                \
            float x = __fmaf_rn(step, (float)r, -1.0f);                        \
            float val = fmaxf(__fmaf_rn(x, Q, P + b1o), 0.0f);                 \
            __nv_bfloat16 vh = __float2bfloat16(val);                          \
            float rest = val - __bfloat162float(vh);                           \
            __nv_bfloat16 vl = __float2bfloat16(rest);                         \
            uint32_t off = SWZ((uint32_t)(r * 128) + cbyte);                   \
            *(__nv_bfloat16*)(smch + H1HI_OFF(qd) + off) = vh;                 \
            *(__nv_bfloat16*)(smch + H1LO_OFF(qd) + off) = vl;                 \
            ++r;                                                               \
        } while (0)

        while (pel--) EMIT_ROW();   // rows before any event (usually 0)

        #pragma unroll 1
        for (int c = 0; c < nchunks; ++c) {
            if (c == nchunks - 1) { CP_WAIT0(); } else { CP_WAIT1(); }
            __syncthreads();
            const float* wb = (const float*)(smch + EVW_OFF(c & 1));
            #pragma unroll 4
            for (int i = 0; i < 32; ++i) {
                float2 ab = evab[e];
                float wv = wb[i * 256 + tid];
                int nem = (int)emc[e];
                ++e;
                P = __fmaf_rn(ab.x, wv, P);
                Q = __fmaf_rn(ab.y, wv, Q);
                if (nem) { do { EMIT_ROW(); } while (--nem); }
            }
            __syncthreads();
            if (c + 2 < nchunks) STAGE_EVW(c + 2);
        }
        while (r < 128) EMIT_ROW();   // safety (ne==0 handled by pel)
    }
    __syncthreads();

    // ---- layer 2: 3-term bf16 MMA (proven path) ----
    #define ISSUE_B2(kc) do {                                                  \
        int bb = (kc) & 1;                                                     \
        const uint4* sh = (const uint4*)g_W2hi + (size_t)m * 4096 + (kc) * 8;  \
        const uint4* sl = (const uint4*)g_W2lo + (size_t)m * 4096 + (kc) * 8;  \
        _Pragma("unroll")                                                      \
        for (int jj = 0; jj < 4; ++jj) {                                       \
            int idx = tid + jj * NTHR;                                         \
            int row = idx >> 3, c16 = idx & 7;                                 \
            uint32_t off = SWZ((uint32_t)(row * 128 + c16 * 16));              \
            cpa16(smb + B2HI_OFF(bb) + off, sh + row * 32 + c16);              \
            cpa16(smb + B2LO_OFF(bb) + off, sl + row * 32 + c16);              \
        }                                                                      \
        CP_COMMIT();                                                           \
    } while (0)

    ISSUE_B2(0);
    ISSUE_B2(1);

    const int mw = w & 3, nw = w >> 2;
    const int m0 = mw * 32, n0 = nw * 64;
    const uint32_t a_row = (uint32_t)(lane & 15);
    const uint32_t a_col = (uint32_t)((lane >> 4) * 16);
    const uint32_t b_row = (uint32_t)((lane & 7) + ((lane & 16) >> 1));
    const uint32_t b_col = (uint32_t)(((lane >> 3) & 1) * 16);
    const int cl2 = (lane & 3) * 2;

    float C[2][8][4];
    #pragma unroll
    for (int mt = 0; mt < 2; ++mt)
        #pragma unroll
        for (int nt = 0; nt < 8; ++nt) {
            int c = n0 + nt * 8 + cl2;
            C[mt][nt][0] = b2f[c]; C[mt][nt][1] = b2f[c + 1];
            C[mt][nt][2] = b2f[c]; C[mt][nt][3] = b2f[c + 1];
        }

    #pragma unroll 1
    for (int s2 = 0; s2 < 4; ++s2) {
        if (s2 == 3) { CP_WAIT0(); } else { CP_WAIT1(); }
        __syncthreads();
        const uint32_t aHIb = smb + H1HI_OFF(s2), aLOb = smb + H1LO_OFF(s2);
        const uint32_t bHIb = smb + B2HI_OFF(s2 & 1), bLOb = smb + B2LO_OFF(s2 & 1);

        #pragma unroll
        for (int k16 = 0; k16 < 4; ++k16) {
            const uint32_t kb2 = (uint32_t)(k16 * 32);
            uint32_t ahi[2][4], alo[2][4], bh[4][4], bl[4][4];
            #pragma unroll
            for (int mt = 0; mt < 2; ++mt) {
                uint32_t aoff = SWZ((uint32_t)((m0 + mt * 16 + a_row) * 128) + kb2 + a_col);
                ldsm4(ahi[mt], aHIb + aoff);
                ldsm4(alo[mt], aLOb + aoff);
            }
            #pragma unroll
            for (int nt2 = 0; nt2 < 4; ++nt2) {
                uint32_t boff = SWZ((uint32_t)((n0 + nt2 * 16 + b_row) * 128) + kb2 + b_col);
                ldsm4(bh[nt2], bHIb + boff);
                ldsm4(bl[nt2], bLOb + boff);
            }
            #pragma unroll
            for (int mt = 0; mt < 2; ++mt)
                #pragma unroll
                for (int nt2 = 0; nt2 < 4; ++nt2)
                    #pragma unroll
                    for (int p2 = 0; p2 < 2; ++p2)
                        mma_bf16(C[mt][nt2 * 2 + p2], ahi[mt], bh[nt2] + 2 * p2);
            #pragma unroll
            for (int mt = 0; mt < 2; ++mt)
                #pragma unroll
                for (int nt2 = 0; nt2 < 4; ++nt2)
                    #pragma unroll
                    for (int p2 = 0; p2 < 2; ++p2)
                        mma_bf16(C[mt][nt2 * 2 + p2], ahi[mt], bl[nt2] + 2 * p2);
            #pragma unroll
            for (int mt = 0; mt < 2; ++mt)
                #pragma unroll
                for (int nt2 = 0; nt2 < 4; ++nt2)
                    #pragma unroll
                    for (int p2 = 0; p2 < 2; ++p2)
                        mma_bf16(C[mt][nt2 * 2 + p2], alo[mt], bh[nt2] + 2 * p2);
        }
        __syncthreads();
        if (s2 + 2 < 4) ISSUE_B2(s2 + 2);
    }

    // ---- h2 epilogue: relu -> f32 [128][129] (aliases H1 region) ----
    float* h2s = (float*)smch;
    #pragma unroll
    for (int mt = 0; mt < 2; ++mt) {
        int rr = m0 + mt * 16 + (lane >> 2);
        #pragma unroll
        for (int nt = 0; nt < 8; ++nt) {
            int c = n0 + nt * 8 + cl2;
            h2s[rr * 129 + c]            = fmaxf(C[mt][nt][0], 0.f);
            h2s[rr * 129 + c + 1]        = fmaxf(C[mt][nt][1], 0.f);
            h2s[(rr + 8) * 129 + c]      = fmaxf(C[mt][nt][2], 0.f);
            h2s[(rr + 8) * 129 + c + 1]  = fmaxf(C[mt][nt][3], 0.f);
        }
    }
    __syncthreads();

    // ---- layer 3 + tanh ----
    if (tid < TG) {
        const float* hr = h2s + tid * 129;
        float a0 = b3[m * OUTD + 0], a1 = b3[m * OUTD + 1], a2 = b3[m * OUTD + 2];
        #pragma unroll 8
        for (int k = 0; k < S2; ++k) {
            float h = hr[k];
            a0 = fmaf(h, w3f[k],       a0);
            a1 = fmaf(h, w3f[128 + k], a1);
            a2 = fmaf(h, w3f[256 + k], a2);
        }
        int p = tile * TG + tid;
        if (p < G) {
            float* o = out + ((size_t)m * G + p) * OUTD;
            o[0] = tanhf(a0);
            o[1] = tanhf(a1);
            o[2] = tanhf(a2);
        }
    }
}

// ---------------- host launcher ----------------------------------------
extern "C" void kernel_launch(void* const* d_in, const int* in_sizes, int n_in,
                              void* d_out, int out_size) {
    const float* x0  = (const float*)d_in[0];
    const float* W0a = (const float*)d_in[1];
    const float* b0a = (const float*)d_in[2];
    const float* W0b = (const float*)d_in[3];
    const float* b0b = (const float*)d_in[4];
    const float* W1  = (const float*)d_in[5];
    const float* b1  = (const float*)d_in[6];
    const float* W2  = (const float*)d_in[7];
    const float* b2  = (const float*)d_in[8];
    const float* W3  = (const float*)d_in[9];
    const float* b3  = (const float*)d_in[10];
    const int*   np  = (const int*)d_in[11];

    int G = out_size / (N_MLP * OUTD);
    int ntiles = (G + TG - 1) / TG;

    prep_c0<<<(N_MLP * S0 * 32 + 255) / 256, 256>>>(x0, W0a, b0a, b0b);
    prep_w1t<<<N_MLP * 128, 256>>>(W1);
    prep_w2<<<512, 256>>>(W2);
    prep_events<<<dim3(ntiles, N_MLP), 512>>>(W0b, np);

    static bool attr_set = false;
    if (!attr_set) {
        cudaFuncSetAttribute(mlp_sweep, cudaFuncAttributeMaxDynamicSharedMemorySize,
                             SMEM_TOTAL);
        attr_set = true;
    }
    dim3 grid(ntiles, N_MLP);
    mlp_sweep<<<grid, NTHR, SMEM_TOTAL>>>(b1, b2, W3, b3, np, (float*)d_out, G);
}

// round 13
// speedup vs baseline: 1.2500x; 1.2500x over previous
#include <cuda_runtime.h>
#include <cuda_bf16.h>
#include <math.h>
#include <stdint.h>

#define N_MLP  16
#define LATENT 1024
#define S0     512
#define S1     256
#define S2     128
#define OUTD   3
#define TG     128
#define NTHR   256

// ---------------- SMEM layout (bytes) --------------------------------
#define H1HI_OFF(q) ((q)*32768u)
#define H1LO_OFF(q) ((q)*32768u + 16384u)
#define EVW_OFF(b)  (131072u + (b)*32768u)
#define B2HI_OFF(b) (131072u + (b)*32768u)
#define B2LO_OFF(b) (131072u + (b)*32768u + 16384u)
#define EVK_OFF   199680u
#define EVAB_OFF  201728u
#define EMC_OFF   209920u
#define SMEM_TOTAL 210944u

#define SWZ(x) ((x) ^ (((x) >> 3) & 0x70u))

// ---------------- device scratch --------------------------------------
__device__ __align__(16) float         g_W1t [N_MLP * S0 * S1];   // [m][k][o]
__device__ __align__(16) __nv_bfloat16 g_W2hi[N_MLP * S2 * S1];
__device__ __align__(16) __nv_bfloat16 g_W2lo[N_MLP * S2 * S1];
__device__ float g_c0[N_MLP * S0];
__device__ __align__(16) uint16_t g_evk [N_MLP * 128 * 1024];
__device__ __align__(16) float2   g_evab[N_MLP * 128 * 1024];
__device__ __align__(16) uint8_t  g_emc [N_MLP * 128 * 1024];
__device__ uint2 g_meta[N_MLP * 128];   // {nep, pel}

// ---------------- helpers ---------------------------------------------
__device__ __forceinline__ uint32_t smem_u32(const void* p) {
    uint32_t a;
    asm("{ .reg .u64 t; cvta.to.shared.u64 t, %1; cvt.u32.u64 %0, t; }"
        : "=r"(a) : "l"(p));
    return a;
}
__device__ __forceinline__ void ldsm4(uint32_t* r, uint32_t addr) {
    asm volatile("ldmatrix.sync.aligned.m8n8.x4.shared.b16 {%0,%1,%2,%3}, [%4];"
                 : "=r"(r[0]), "=r"(r[1]), "=r"(r[2]), "=r"(r[3]) : "r"(addr));
}
__device__ __forceinline__ void mma_bf16(float* d, const uint32_t* a, const uint32_t* b) {
    asm volatile(
        "mma.sync.aligned.m16n8k16.row.col.f32.bf16.bf16.f32 "
        "{%0,%1,%2,%3}, {%4,%5,%6,%7}, {%8,%9}, {%0,%1,%2,%3};"
        : "+f"(d[0]), "+f"(d[1]), "+f"(d[2]), "+f"(d[3])
        : "r"(a[0]), "r"(a[1]), "r"(a[2]), "r"(a[3]), "r"(b[0]), "r"(b[1]));
}
__device__ __forceinline__ void cpa16(uint32_t dst, const void* src) {
    asm volatile("cp.async.cg.shared.global [%0], [%1], 16;"
                 :: "r"(dst), "l"(src) : "memory");
}
#define CP_COMMIT() asm volatile("cp.async.commit_group;" ::: "memory")
#define CP_WAIT1()  asm volatile("cp.async.wait_group 1;" ::: "memory")
#define CP_WAIT0()  asm volatile("cp.async.wait_group 0;" ::: "memory")

// ---------------- prep: c0 --------------------------------------------
__global__ void prep_c0(const float* __restrict__ x0,
                        const float* __restrict__ W0a,
                        const float* __restrict__ b0a,
                        const float* __restrict__ b0b) {
    int w    = (blockIdx.x * blockDim.x + threadIdx.x) >> 5;
    int lane = threadIdx.x & 31;
    if (w >= N_MLP * S0) return;
    const float* row = W0a + (size_t)w * LATENT;
    float s = 0.f;
    #pragma unroll 4
    for (int i = lane; i < LATENT; i += 32) s += row[i] * x0[i];
    #pragma unroll
    for (int off = 16; off; off >>= 1) s += __shfl_xor_sync(0xffffffffu, s, off);
    if (lane == 0) g_c0[w] = s + b0a[w] + b0b[w];
}

// ---------------- prep: W1 transpose via 32x33 tiles --------------------
__global__ void prep_w1t(const float* __restrict__ W1) {
    __shared__ float tl[32][33];
    int b = blockIdx.x;                 // m*128 + kt*8 + ot
    int m = b >> 7, rem = b & 127, kt = rem >> 3, ot = rem & 7;
    int tx = threadIdx.x & 31, ty = threadIdx.x >> 5;   // 256 thr
    const float* src = W1 + ((size_t)m * 256 + ot * 32) * 512 + kt * 32;
    #pragma unroll
    for (int j = 0; j < 4; ++j)
        tl[ty + j * 8][tx] = src[(size_t)(ty + j * 8) * 512 + tx];
    __syncthreads();
    float* dst = g_W1t + ((size_t)m * 512 + kt * 32) * 256 + ot * 32;
    #pragma unroll
    for (int j = 0; j < 4; ++j)
        dst[(size_t)(ty + j * 8) * 256 + tx] = tl[tx][ty + j * 8];
}

// ---------------- prep: W2 split ----------------------------------------
__global__ void prep_w2(const float* __restrict__ W2) {
    const int t2 = N_MLP * S2 * S1;
    for (int i = blockIdx.x * blockDim.x + threadIdx.x; i < t2;
         i += gridDim.x * blockDim.x) {
        float v = W2[i];
        __nv_bfloat16 h = __float2bfloat16(v);
        g_W2hi[i] = h;
        g_W2lo[i] = __float2bfloat16(v - __bfloat162float(h));
    }
}

// ---------------- prep: ReLU crossing events (match_any scatter) --------
__device__ __forceinline__ bool actv(float wx, float al, float step, int rr) {
    return fmaf(wx, fmaf(step, (float)rr, -1.0f), al) > 0.0f;
}

__global__ void prep_events(const float* __restrict__ W0b,
                            const int*   __restrict__ n_ptr) {
    __shared__ float    salf[512], sbet[512];
    __shared__ int      slohi[512];
    __shared__ int      scnt[129];
    __shared__ int      offA[16][128], offR[16][128];  // counts, then offsets
    __shared__ __align__(16) uint16_t sevk[1024];
    __shared__ __align__(16) float2   sevab[1024];
    __shared__ __align__(16) uint8_t  serow[1032];
    __shared__ __align__(16) uint8_t  semc[1024];

    const int tile = blockIdx.x, m = blockIdx.y, t = threadIdx.x;  // 128 thr
    const int wrp = t >> 5, lane = t & 31;
    const int n = *n_ptr;
    const float step = 2.0f / (float)(n - 1);
    const float gy = __fmaf_rn(step, (float)tile, -1.0f);

    // zero count tables
    #pragma unroll
    for (int i = 0; i < 16; ++i) { offA[i][t] = 0; offR[i][t] = 0; }

    // phase 1: per-neuron boundary (analytic + exact fixup), 4 per thread
    for (int k = t; k < 512; k += 128) {
        float c0 = g_c0[m * 512 + k];
        float wx = W0b[(size_t)(m * 512 + k) * 2];
        float wy = W0b[(size_t)(m * 512 + k) * 2 + 1];
        float al = __fmaf_rn(wy, gy, c0);
        int lo, hi;
        if (wx > 0.0f) {
            float rf = (1.0f - al / wx) / step;
            int c = (int)floorf(rf) - 2;
            c = c < 0 ? 0 : (c > 128 ? 128 : c);
            while (c < 128 && !actv(wx, al, step, c)) ++c;
            while (c > 0 && actv(wx, al, step, c - 1)) --c;
            lo = c; hi = 128;
        } else if (wx < 0.0f) {
            if (!actv(wx, al, step, 0)) { lo = 128; hi = 128; }
            else {
                float rf = (1.0f - al / wx) / step;
                int c = (int)floorf(rf) - 2;
                c = c < 1 ? 1 : (c > 128 ? 128 : c);
                while (c < 128 && actv(wx, al, step, c)) ++c;
                while (c > 1 && !actv(wx, al, step, c - 1)) --c;
                lo = 0; hi = c;
            }
        } else {
            if (al > 0.0f) { lo = 0; hi = 128; } else { lo = 128; hi = 128; }
        }
        salf[k] = al; sbet[k] = wx; slohi[k] = (lo << 8) | hi;
    }
    __syncthreads();

    // phase 2: per-(group,bucket) counts via match_any (group = k/32, k-ordered)
    #pragma unroll
    for (int i = 0; i < 4; ++i) {
        int g = wrp * 4 + i;
        int v = slohi[g * 32 + lane];
        int lo = v >> 8, hi = v & 255;
        bool vA = lo < hi;
        bool vR = vA && (hi < 128);
        unsigned bA = __ballot_sync(0xffffffffu, vA);
        unsigned bR = __ballot_sync(0xffffffffu, vR);
        unsigned mA = __match_any_sync(0xffffffffu, lo) & bA;
        unsigned mR = __match_any_sync(0xffffffffu, hi) & bR;
        if (vA && lane == __ffs(mA) - 1) offA[g][lo] = __popc(mA);
        if (vR && lane == __ffs(mR) - 1) offR[g][hi] = __popc(mR);
    }
    __syncthreads();

    // phase 3: bucket totals + block scan + per-group offsets (thread = bucket)
    int cAr[16], cRr[16];
    {
        int totA = 0, totR = 0;
        #pragma unroll
        for (int g = 0; g < 16; ++g) {
            cAr[g] = offA[g][t]; totA += cAr[g];
            cRr[g] = offR[g][t]; totR += cRr[g];
        }
        if (t == 0) scnt[0] = 0;
        scnt[t + 1] = totA + totR;
    }
    __syncthreads();
    #pragma unroll
    for (int d = 1; d < 128; d <<= 1) {
        int i = t + 1;
        int v = (i - d >= 1) ? scnt[i - d] : 0;
        __syncthreads();
        scnt[i] += v;
        __syncthreads();
    }
    {
        int run = scnt[t];
        #pragma unroll
        for (int g = 0; g < 16; ++g) { offA[g][t] = run; run += cAr[g]; }
        #pragma unroll
        for (int g = 0; g < 16; ++g) { offR[g][t] = run; run += cRr[g]; }
    }
    __syncthreads();

    // phase 4: scatter (deterministic: groups k-asc, lanes k-asc, ADDs then REMOVEs)
    #pragma unroll
    for (int i = 0; i < 4; ++i) {
        int g = wrp * 4 + i;
        int k = g * 32 + lane;
        int v = slohi[k];
        int lo = v >> 8, hi = v & 255;
        bool vA = lo < hi;
        bool vR = vA && (hi < 128);
        unsigned bA = __ballot_sync(0xffffffffu, vA);
        unsigned bR = __ballot_sync(0xffffffffu, vR);
        unsigned mA = __match_any_sync(0xffffffffu, lo) & bA;
        unsigned mR = __match_any_sync(0xffffffffu, hi) & bR;
        unsigned below = (1u << lane) - 1u;
        if (vA) {
            int pos = offA[g][lo] + __popc(mA & below);
            sevk[pos] = (uint16_t)k;
            sevab[pos] = make_float2(salf[k], sbet[k]);
        }
        if (vR) {
            int pos = offR[g][hi] + __popc(mR & below);
            sevk[pos] = (uint16_t)k;
            sevab[pos] = make_float2(-salf[k], -sbet[k]);
        }
    }
    __syncthreads();

    const int ne = scnt[128];
    const int nep = (ne + 31) & ~31;
    for (int i = ne + t; i < 1024; i += 128) {
        sevk[i] = 0; sevab[i] = make_float2(0.f, 0.f);
    }

    // serow via binary search over scnt (balanced); serow[e]=bucket(e), 128 if e>=ne
    for (int e = t; e <= 1024; e += 128) {
        int b2 = 0;
        #pragma unroll
        for (int s = 128; s; s >>= 1)
            if (b2 + s <= 128 && scnt[b2 + s] <= e) b2 += s;
        serow[e] = (uint8_t)b2;
    }
    __syncthreads();
    for (int e = t; e < 1024; e += 128) semc[e] = serow[e + 1] - serow[e];
    __syncthreads();

    const size_t base = (size_t)m * gridDim.x + tile;
    if (t == 0) g_meta[base] = make_uint2((uint32_t)nep, (uint32_t)serow[0]);
    ((uint4*)(g_evk + base * 1024))[t] = ((uint4*)sevk)[t];
    #pragma unroll
    for (int j = 0; j < 4; ++j)
        ((uint4*)(g_evab + base * 1024))[t + j * 128] = ((uint4*)sevab)[t + j * 128];
    if (t < 64) ((uint4*)(g_emc + base * 1024))[t] = ((uint4*)semc)[t];
}

// ---------------- main kernel (R11-verbatim, proven) ---------------------
__global__ __launch_bounds__(NTHR, 1)
void mlp_sweep(const float* __restrict__ b1,
               const float* __restrict__ b2,
               const float* __restrict__ W3,
               const float* __restrict__ b3,
               const int*   __restrict__ n_ptr,
               float*       __restrict__ out,
               int G) {
    extern __shared__ char smch[];
    const uint32_t smb = smem_u32(smch);
    float*    b1f  = (float*)(smch + 196608);
    float*    b2f  = (float*)(smch + 197632);
    float*    w3f  = (float*)(smch + 198144);
    uint16_t* evk  = (uint16_t*)(smch + EVK_OFF);
    float2*   evab = (float2*)(smch + EVAB_OFF);
    uint8_t*  emc  = (uint8_t*)(smch + EMC_OFF);

    const int m = blockIdx.y, tile = blockIdx.x;
    const int tid = threadIdx.x, w = tid >> 5, lane = tid & 31;
    const int n = *n_ptr;
    const float step = 2.0f / (float)(n - 1);

    // ---- stage consts + events ----
    b1f[tid] = b1[m * 256 + tid];
    if (tid < 128) b2f[tid] = b2[m * 128 + tid];
    for (int i = tid; i < 384; i += NTHR) w3f[i] = W3[(size_t)m * 384 + i];
    const size_t evbase = (size_t)m * gridDim.x + tile;
    if (tid < 128) ((uint4*)evk)[tid] = ((const uint4*)(g_evk + evbase * 1024))[tid];
    #pragma unroll
    for (int j = 0; j < 2; ++j)
        ((uint4*)evab)[tid + j * NTHR] =
            ((const uint4*)(g_evab + evbase * 1024))[tid + j * NTHR];
    if (tid < 64) ((uint4*)emc)[tid] = ((const uint4*)(g_emc + evbase * 1024))[tid];
    const uint2 meta = g_meta[evbase];
    const int nep = (int)meta.x;
    int pel = (int)meta.y;
    __syncthreads();

    const int nchunks = nep >> 5;

    #define STAGE_EVW(c) do {                                                  \
        int bb = (c) & 1;                                                      \
        _Pragma("unroll")                                                      \
        for (int jj = 0; jj < 8; ++jj) {                                       \
            int idx = tid + jj * NTHR;                                         \
            int row = idx >> 6, c16 = idx & 63;                                \
            int k = (int)evk[(c) * 32 + row];                                  \
            cpa16(smb + EVW_OFF(bb) + (uint32_t)(row * 1024 + c16 * 16),       \
                  g_W1t + ((size_t)m * 512 + k) * 256 + c16 * 4);              \
        }                                                                      \
        CP_COMMIT();                                                           \
    } while (0)

    if (nchunks > 0) { STAGE_EVW(0); if (nchunks > 1) STAGE_EVW(1); }

    // ---- layer1 flat event sweep: thread t owns column o = t ----
    {
        const float b1o = b1f[tid];
        const uint32_t qd = (uint32_t)tid >> 6;
        const uint32_t cbyte = (uint32_t)((tid & 63) * 2);
        float P = 0.f, Q = 0.f;
        int r = 0, e = 0;

        #define EMIT_ROW() do {                                                \
            float x = __fmaf_rn(step, (float)r, -1.0f);                        \
            float val = fmaxf(__fmaf_rn(x, Q, P + b1o), 0.0f);                 \
            __nv_bfloat16 vh = __float2bfloat16(val);                          \
            float rest = val - __bfloat162float(vh);                           \
            __nv_bfloat16 vl = __float2bfloat16(rest);                         \
            uint32_t off = SWZ((uint32_t)(r * 128) + cbyte);                   \
            *(__nv_bfloat16*)(smch + H1HI_OFF(qd) + off) = vh;                 \
            *(__nv_bfloat16*)(smch + H1LO_OFF(qd) + off) = vl;                 \
            ++r;                                                               \
        } while (0)

        while (pel--) EMIT_ROW();   // rows before any event (usually 0)

        #pragma unroll 1
        for (int c = 0; c < nchunks; ++c) {
            if (c == nchunks - 1) { CP_WAIT0(); } else { CP_WAIT1(); }
            __syncthreads();
            const float* wb = (const float*)(smch + EVW_OFF(c & 1));
            #pragma unroll 4
            for (int i = 0; i < 32; ++i) {
                float2 ab = evab[e];
                float wv = wb[i * 256 + tid];
                int nem = (int)emc[e];
                ++e;
                P = __fmaf_rn(ab.x, wv, P);
                Q = __fmaf_rn(ab.y, wv, Q);
                if (nem) { do { EMIT_ROW(); } while (--nem); }
            }
            __syncthreads();
            if (c + 2 < nchunks) STAGE_EVW(c + 2);
        }
        while (r < 128) EMIT_ROW();   // safety (ne==0 handled by pel)
    }
    __syncthreads();

    // ---- layer 2: 3-term bf16 MMA (proven path) ----
    #define ISSUE_B2(kc) do {                                                  \
        int bb = (kc) & 1;                                                     \
        const uint4* sh = (const uint4*)g_W2hi + (size_t)m * 4096 + (kc) * 8;  \
        const uint4* sl = (const uint4*)g_W2lo + (size_t)m * 4096 + (kc) * 8;  \
        _Pragma("unroll")                                                      \
        for (int jj = 0; jj < 4; ++jj) {                                       \
            int idx = tid + jj * NTHR;                                         \
            int row = idx >> 3, c16 = idx & 7;                                 \
            uint32_t off = SWZ((uint32_t)(row * 128 + c16 * 16));              \
            cpa16(smb + B2HI_OFF(bb) + off, sh + row * 32 + c16);              \
            cpa16(smb + B2LO_OFF(bb) + off, sl + row * 32 + c16);              \
        }                                                                      \
        CP_COMMIT();                                                           \
    } while (0)

    ISSUE_B2(0);
    ISSUE_B2(1);

    const int mw = w & 3, nw = w >> 2;
    const int m0 = mw * 32, n0 = nw * 64;
    const uint32_t a_row = (uint32_t)(lane & 15);
    const uint32_t a_col = (uint32_t)((lane >> 4) * 16);
    const uint32_t b_row = (uint32_t)((lane & 7) + ((lane & 16) >> 1));
    const uint32_t b_col = (uint32_t)(((lane >> 3) & 1) * 16);
    const int cl2 = (lane & 3) * 2;

    float C[2][8][4];
    #pragma unroll
    for (int mt = 0; mt < 2; ++mt)
        #pragma unroll
        for (int nt = 0; nt < 8; ++nt) {
            int c = n0 + nt * 8 + cl2;
            C[mt][nt][0] = b2f[c]; C[mt][nt][1] = b2f[c + 1];
            C[mt][nt][2] = b2f[c]; C[mt][nt][3] = b2f[c + 1];
        }

    #pragma unroll 1
    for (int s2 = 0; s2 < 4; ++s2) {
        if (s2 == 3) { CP_WAIT0(); } else { CP_WAIT1(); }
        __syncthreads();
        const uint32_t aHIb = smb + H1HI_OFF(s2), aLOb = smb + H1LO_OFF(s2);
        const uint32_t bHIb = smb + B2HI_OFF(s2 & 1), bLOb = smb + B2LO_OFF(s2 & 1);

        #pragma unroll
        for (int k16 = 0; k16 < 4; ++k16) {
            const uint32_t kb2 = (uint32_t)(k16 * 32);
            uint32_t ahi[2][4], alo[2][4], bh[4][4], bl[4][4];
            #pragma unroll
            for (int mt = 0; mt < 2; ++mt) {
                uint32_t aoff = SWZ((uint32_t)((m0 + mt * 16 + a_row) * 128) + kb2 + a_col);
                ldsm4(ahi[mt], aHIb + aoff);
                ldsm4(alo[mt], aLOb + aoff);
            }
            #pragma unroll
            for (int nt2 = 0; nt2 < 4; ++nt2) {
                uint32_t boff = SWZ((uint32_t)((n0 + nt2 * 16 + b_row) * 128) + kb2 + b_col);
                ldsm4(bh[nt2], bHIb + boff);
                ldsm4(bl[nt2], bLOb + boff);
            }
            #pragma unroll
            for (int mt = 0; mt < 2; ++mt)
                #pragma unroll
                for (int nt2 = 0; nt2 < 4; ++nt2)
                    #pragma unroll
                    for (int p2 = 0; p2 < 2; ++p2)
                        mma_bf16(C[mt][nt2 * 2 + p2], ahi[mt], bh[nt2] + 2 * p2);
            #pragma unroll
            for (int mt = 0; mt < 2; ++mt)
                #pragma unroll
                for (int nt2 = 0; nt2 < 4; ++nt2)
                    #pragma unroll
                    for (int p2 = 0; p2 < 2; ++p2)
                        mma_bf16(C[mt][nt2 * 2 + p2], ahi[mt], bl[nt2] + 2 * p2);
            #pragma unroll
            for (int mt = 0; mt < 2; ++mt)
                #pragma unroll
                for (int nt2 = 0; nt2 < 4; ++nt2)
                    #pragma unroll
                    for (int p2 = 0; p2 < 2; ++p2)
                        mma_bf16(C[mt][nt2 * 2 + p2], alo[mt], bh[nt2] + 2 * p2);
        }
        __syncthreads();
        if (s2 + 2 < 4) ISSUE_B2(s2 + 2);
    }

    // ---- h2 epilogue: relu -> f32 [128][129] (aliases H1 region) ----
    float* h2s = (float*)smch;
    #pragma unroll
    for (int mt = 0; mt < 2; ++mt) {
        int rr = m0 + mt * 16 + (lane >> 2);
        #pragma unroll
        for (int nt = 0; nt < 8; ++nt) {
            int c = n0 + nt * 8 + cl2;
            h2s[rr * 129 + c]            = fmaxf(C[mt][nt][0], 0.f);
            h2s[rr * 129 + c + 1]        = fmaxf(C[mt][nt][1], 0.f);
            h2s[(rr + 8) * 129 + c]      = fmaxf(C[mt][nt][2], 0.f);
            h2s[(rr + 8) * 129 + c + 1]  = fmaxf(C[mt][nt][3], 0.f);
        }
    }
    __syncthreads();

    // ---- layer 3 + tanh ----
    if (tid < TG) {
        const float* hr = h2s + tid * 129;
        float a0 = b3[m * OUTD + 0], a1 = b3[m * OUTD + 1], a2 = b3[m * OUTD + 2];
        #pragma unroll 8
        for (int k = 0; k < S2; ++k) {
            float h = hr[k];
            a0 = fmaf(h, w3f[k],       a0);
            a1 = fmaf(h, w3f[128 + k], a1);
            a2 = fmaf(h, w3f[256 + k], a2);
        }
        int p = tile * TG + tid;
        if (p < G) {
            float* o = out + ((size_t)m * G + p) * OUTD;
            o[0] = tanhf(a0);
            o[1] = tanhf(a1);
            o[2] = tanhf(a2);
        }
    }
}

// ---------------- host launcher ----------------------------------------
extern "C" void kernel_launch(void* const* d_in, const int* in_sizes, int n_in,
                              void* d_out, int out_size) {
    const float* x0  = (const float*)d_in[0];
    const float* W0a = (const float*)d_in[1];
    const float* b0a = (const float*)d_in[2];
    const float* W0b = (const float*)d_in[3];
    const float* b0b = (const float*)d_in[4];
    const float* W1  = (const float*)d_in[5];
    const float* b1  = (const float*)d_in[6];
    const float* W2  = (const float*)d_in[7];
    const float* b2  = (const float*)d_in[8];
    const float* W3  = (const float*)d_in[9];
    const float* b3  = (const float*)d_in[10];
    const int*   np  = (const int*)d_in[11];

    int G = out_size / (N_MLP * OUTD);
    int ntiles = (G + TG - 1) / TG;

    prep_c0<<<(N_MLP * S0 * 32 + 255) / 256, 256>>>(x0, W0a, b0a, b0b);
    prep_w1t<<<N_MLP * 128, 256>>>(W1);
    prep_w2<<<512, 256>>>(W2);
    prep_events<<<dim3(ntiles, N_MLP), 128>>>(W0b, np);

    static bool attr_set = false;
    if (!attr_set) {
        cudaFuncSetAttribute(mlp_sweep, cudaFuncAttributeMaxDynamicSharedMemorySize,
                             SMEM_TOTAL);
        attr_set = true;
    }
    dim3 grid(ntiles, N_MLP);
    mlp_sweep<<<grid, NTHR, SMEM_TOTAL>>>(b1, b2, W3, b3, np, (float*)d_out, G);
}